// round 2
// baseline (speedup 1.0000x reference)
#include <cuda_runtime.h>

#define DD 64
#define HH_ 256
#define WW 256
#define HWSZ (HH_*WW)          // 65536
#define DHW (DD*HH_*WW)        // 4194304
#define CASC 3

// ---- conv tile config ----
#define TD 4
#define TH 8
#define TW 32
#define ID_ (TD+4)             // 8
#define IH_ (TH+4)             // 12
#define IW_ (TW+4)             // 36
#define NIN (ID_*IH_*IW_)      // 3456
#define HD (TD+2)              // 6
#define HHt (TH+2)             // 10
#define HWt (TW+2)             // 34
#define NHID (HD*HHt*HWt)      // 2040

// smem layout (in floats)
#define OFF_HID 0                        // float4 region: 2*NHID float4
#define OFF_IN  (2*NHID*4)               // 16320
#define OFF_W1  (OFF_IN + NIN)           // 19776  (16B aligned)
#define OFF_W2  (OFF_W1 + 216)           // 19992  (16B aligned)
#define OFF_B1  (OFF_W2 + 216)           // 20208
#define OFF_B2  (OFF_B1 + 8)             // 20216
#define SMEM_FLOATS (OFF_B2 + 8)         // 20224
#define SMEM_BYTES (SMEM_FLOATS*4)       // 80896

// ---- persistent state (device globals: allowed scratch) ----
__device__ float g_t[DHW];
__device__ float g_z[DHW];
__device__ float g_dx[DHW];
__device__ float g_dy[DHW];
__device__ float g_dz[DHW];
__device__ float g_p[DHW];
__device__ float g_q[DHW];
__device__ float g_s[DHW];
__device__ float g_zb[DHW];

// ---------------- K0: init state from image ----------------
__global__ void k_init(const float* __restrict__ img, float* __restrict__ out) {
    int i = blockIdx.x * blockDim.x + threadIdx.x;
    if (i < DHW) {
        float v = img[i];
        g_t[i] = v;
        out[i] = v;
        g_p[i] = 0.f; g_q[i] = 0.f; g_s[i] = 0.f;
    }
}

// ---------------- K1: z = t + (sino - sum_d t)/D ----------------
__global__ void k_z(const float* __restrict__ sino) {
    int hw = blockIdx.x * blockDim.x + threadIdx.x;
    if (hw >= HWSZ) return;
    float sum = 0.f;
    #pragma unroll 8
    for (int d = 0; d < DD; d++) sum += g_t[d * HWSZ + hw];
    float r = (sino[hw] - sum) * (1.0f / DD);
    #pragma unroll 8
    for (int d = 0; d < DD; d++) g_z[d * HWSZ + hw] = g_t[d * HWSZ + hw] + r;
}

// ---------------- K1b: forward differences ----------------
__global__ void k_diff() {
    int i = blockIdx.x * blockDim.x + threadIdx.x;
    if (i >= DHW) return;
    int w = i & (WW - 1);
    int h = (i >> 8) & (HH_ - 1);
    int d = i >> 16;
    float zc = g_z[i];
    g_dx[i] = (w < WW - 1) ? g_z[i + 1]    - zc : 0.f;
    g_dy[i] = (h < HH_ - 1) ? g_z[i + WW]   - zc : 0.f;
    g_dz[i] = (d < DD - 1) ? g_z[i + HWSZ] - zc : 0.f;
}

// ---------------- K2: fused conv block (1->8 relu 8->1) + momentum update ----------------
__global__ __launch_bounds__(256, 2) void k_conv(
    const float* __restrict__ W1g, const float* __restrict__ B1g,
    const float* __restrict__ W2g, const float* __restrict__ B2g,
    const float* __restrict__ ntx, const float* __restrict__ nty,
    const float* __restrict__ ntz, const float* __restrict__ nt,
    int casc)
{
    extern __shared__ float smem[];
    float4* sHid4 = (float4*)smem;                 // [2*NHID] float4
    float*  sIn   = smem + OFF_IN;
    float*  sW1   = smem + OFF_W1;                 // [k][c] layout, 27x8
    float*  sW2   = smem + OFF_W2;
    float*  sB1   = smem + OFF_B1;
    float*  sB2   = smem + OFF_B2;

    int tid = threadIdx.x;
    int b   = blockIdx.z >> 4;                     // block type 0..3
    int dt  = blockIdx.z & 15;
    int d0 = dt * TD, h0 = blockIdx.y * TH, w0 = blockIdx.x * TW;

    const float* in   = (b == 0) ? g_dx : (b == 1) ? g_dy : (b == 2) ? g_dz : g_z;
    const float* oldv = (b == 0) ? g_p  : (b == 1) ? g_q  : (b == 2) ? g_s  : g_t;
    float*       dst  = (b == 0) ? g_p  : (b == 1) ? g_q  : (b == 2) ? g_s  : g_zb;
    float eta = ((b == 0) ? ntx : (b == 1) ? nty : (b == 2) ? ntz : nt)[casc];

    // weights -> smem, transposed to [k*8+c]
    for (int i = tid; i < 216; i += 256) {
        int c = i / 27, k = i % 27;
        sW1[k * 8 + c] = W1g[b * 216 + i];
        sW2[k * 8 + c] = W2g[b * 216 + i];
    }
    if (tid < 8) sB1[tid] = B1g[b * 8 + tid];
    if (tid == 0) sB2[0] = B2g[b];

    // input tile with halo 2 (zero pad outside volume)
    for (int i = tid; i < NIN; i += 256) {
        int lw = i % IW_;
        int t2 = i / IW_;
        int lh = t2 % IH_;
        int ld = t2 / IH_;
        int gd = d0 + ld - 2, gh = h0 + lh - 2, gw = w0 + lw - 2;
        float v = 0.f;
        if (gd >= 0 && gd < DD && gh >= 0 && gh < HH_ && gw >= 0 && gw < WW)
            v = in[(gd * HH_ + gh) * WW + gw];
        sIn[i] = v;
    }
    __syncthreads();

    // ---- conv1: hidden voxels with halo 1, 8 channels ----
    // NOTE: hidden voxels whose GLOBAL position lies outside the volume must be
    // ZERO (conv2's SAME padding pads the hidden field with zeros), not computed.
    const float4* sW1f4 = (const float4*)sW1;
    for (int p = 0; p < 2; p++) {
        float acc[4][8];
        int base[4];
        #pragma unroll
        for (int j = 0; j < 4; j++) {
            int hv = (p * 4 + j) * 256 + tid;
            int hvc = hv < NHID ? hv : 0;
            int hw_ = hvc % HWt;
            int t2  = hvc / HWt;
            int hh  = t2 % HHt;
            int hd  = t2 / HHt;
            base[j] = (hd * IH_ + hh) * IW_ + hw_;
            #pragma unroll
            for (int c = 0; c < 8; c++) acc[j][c] = sB1[c];
        }
        #pragma unroll
        for (int kd = 0; kd < 3; kd++)
        #pragma unroll
        for (int kh = 0; kh < 3; kh++) {
            int rowoff = (kd * IH_ + kh) * IW_;
            #pragma unroll
            for (int kw = 0; kw < 3; kw++) {
                int k = kd * 9 + kh * 3 + kw;
                float4 wa = sW1f4[2 * k];
                float4 wb = sW1f4[2 * k + 1];
                int off = rowoff + kw;
                #pragma unroll
                for (int j = 0; j < 4; j++) {
                    float v = sIn[base[j] + off];
                    acc[j][0] = fmaf(wa.x, v, acc[j][0]);
                    acc[j][1] = fmaf(wa.y, v, acc[j][1]);
                    acc[j][2] = fmaf(wa.z, v, acc[j][2]);
                    acc[j][3] = fmaf(wa.w, v, acc[j][3]);
                    acc[j][4] = fmaf(wb.x, v, acc[j][4]);
                    acc[j][5] = fmaf(wb.y, v, acc[j][5]);
                    acc[j][6] = fmaf(wb.z, v, acc[j][6]);
                    acc[j][7] = fmaf(wb.w, v, acc[j][7]);
                }
            }
        }
        #pragma unroll
        for (int j = 0; j < 4; j++) {
            int hv = (p * 4 + j) * 256 + tid;
            if (hv < NHID) {
                // global coordinate of this hidden voxel
                int hw_ = hv % HWt;
                int t2  = hv / HWt;
                int hh  = t2 % HHt;
                int hd  = t2 / HHt;
                int gd = d0 + hd - 1, gh = h0 + hh - 1, gw = w0 + hw_ - 1;
                bool inside = (gd >= 0 && gd < DD && gh >= 0 && gh < HH_ &&
                               gw >= 0 && gw < WW);
                float4 lo, hi;
                if (inside) {
                    lo = make_float4(fmaxf(acc[j][0], 0.f), fmaxf(acc[j][1], 0.f),
                                     fmaxf(acc[j][2], 0.f), fmaxf(acc[j][3], 0.f));
                    hi = make_float4(fmaxf(acc[j][4], 0.f), fmaxf(acc[j][5], 0.f),
                                     fmaxf(acc[j][6], 0.f), fmaxf(acc[j][7], 0.f));
                } else {
                    lo = make_float4(0.f, 0.f, 0.f, 0.f);
                    hi = make_float4(0.f, 0.f, 0.f, 0.f);
                }
                sHid4[hv] = lo;
                sHid4[NHID + hv] = hi;
            }
        }
    }
    __syncthreads();

    // ---- conv2: each thread -> 4 outputs along d at fixed (oh, ow) ----
    int ow = tid & 31;
    int oh = tid >> 5;
    const float4* sW2f4 = (const float4*)sW2;
    float accO[4];
    {
        float bb = sB2[0];
        #pragma unroll
        for (int od = 0; od < 4; od++) accO[od] = bb;
    }
    #pragma unroll
    for (int kd = 0; kd < 3; kd++)
    #pragma unroll
    for (int kh = 0; kh < 3; kh++) {
        int hr = oh + kh;
        #pragma unroll
        for (int kw = 0; kw < 3; kw++) {
            int k = kd * 9 + kh * 3 + kw;
            float4 wa = sW2f4[2 * k];
            float4 wb = sW2f4[2 * k + 1];
            int cidx = hr * HWt + ow + kw;
            #pragma unroll
            for (int od = 0; od < 4; od++) {
                int v = (od + kd) * (HHt * HWt) + cidx;
                float4 h0 = sHid4[v];
                float4 h1 = sHid4[NHID + v];
                accO[od] = fmaf(wa.x, h0.x, accO[od]);
                accO[od] = fmaf(wa.y, h0.y, accO[od]);
                accO[od] = fmaf(wa.z, h0.z, accO[od]);
                accO[od] = fmaf(wa.w, h0.w, accO[od]);
                accO[od] = fmaf(wb.x, h1.x, accO[od]);
                accO[od] = fmaf(wb.y, h1.y, accO[od]);
                accO[od] = fmaf(wb.z, h1.z, accO[od]);
                accO[od] = fmaf(wb.w, h1.w, accO[od]);
            }
        }
    }
    // fused momentum update: dst = old + eta*(old - new)
    #pragma unroll
    for (int od = 0; od < 4; od++) {
        int gi = ((d0 + od) * HH_ + (h0 + oh)) * WW + (w0 + ow);
        float old = oldv[gi];
        dst[gi] = old + eta * (old - accO[od]);
    }
}

// ---------------- K3: t = divT(p,q,s) + z_ ; write output slice ----------------
__global__ void k_tupd(float* __restrict__ out, int casc) {
    int i = blockIdx.x * blockDim.x + threadIdx.x;
    if (i >= DHW) return;
    int w = i & (WW - 1);
    int h = (i >> 8) & (HH_ - 1);
    int d = i >> 16;
    float v = g_zb[i];
    v += ((w > 0) ? g_p[i - 1]    : 0.f) - ((w < WW - 1) ? g_p[i] : 0.f);
    v += ((h > 0) ? g_q[i - WW]   : 0.f) - ((h < HH_ - 1) ? g_q[i] : 0.f);
    v += ((d > 0) ? g_s[i - HWSZ] : 0.f) - ((d < DD - 1) ? g_s[i] : 0.f);
    g_t[i] = v;
    out[(casc + 1) * DHW + i] = v;
}

extern "C" void kernel_launch(void* const* d_in, const int* in_sizes, int n_in,
                              void* d_out, int out_size) {
    const float* image = (const float*)d_in[0];
    const float* sino  = (const float*)d_in[1];
    const float* W1    = (const float*)d_in[2];
    const float* B1    = (const float*)d_in[3];
    const float* W2    = (const float*)d_in[4];
    const float* B2    = (const float*)d_in[5];
    const float* ntx   = (const float*)d_in[6];
    const float* nty   = (const float*)d_in[7];
    const float* ntz   = (const float*)d_in[8];
    const float* nt    = (const float*)d_in[9];
    float* out = (float*)d_out;

    cudaFuncSetAttribute((const void*)k_conv,
                         cudaFuncAttributeMaxDynamicSharedMemorySize, SMEM_BYTES);

    k_init<<<DHW / 256, 256>>>(image, out);
    for (int c = 0; c < CASC; c++) {
        k_z<<<HWSZ / 256, 256>>>(sino);
        k_diff<<<DHW / 256, 256>>>();
        dim3 grid(WW / TW, HH_ / TH, (DD / TD) * 4);   // (8, 32, 64)
        k_conv<<<grid, 256, SMEM_BYTES>>>(W1, B1, W2, B2, ntx, nty, ntz, nt, c);
        k_tupd<<<DHW / 256, 256>>>(out, c);
    }
}

// round 3
// speedup vs baseline: 2.2091x; 2.2091x over previous
#include <cuda_runtime.h>

#define DD 64
#define HH_ 256
#define WW 256
#define HWSZ 65536
#define DHW 4194304
#define CASC 3

#define TH 16
#define TW 32
#define IHP 20              // TH+4
#define IWP 36              // TW+4
#define NINP (IHP*IWP)      // 720
#define HHP 18              // TH+2
#define HWP 34              // TW+2
#define NHP (HHP*HWP)       // 612

// smem byte offsets (16B aligned where needed)
#define OFF_HA 0
#define OFF_HB (OFF_HA + 3*NHP*16)     // 29376
#define OFF_W1 (OFF_HB + 3*NHP*16)     // 58752
#define OFF_W2 (OFF_W1 + 108*8)        // 59616
#define OFF_B1 (OFF_W2 + 108*8)        // 60480
#define OFF_IN (OFF_B1 + 4*8)          // 60512
#define OFF_B2 (OFF_IN + 3*NINP*4)     // 69152
#define SMEM_BYTES (OFF_B2 + 16)       // 69168

typedef unsigned long long u64;

__device__ float g_t[DHW];
__device__ float g_z[DHW];
__device__ float g_p[DHW];
__device__ float g_q[DHW];
__device__ float g_s[DHW];
__device__ float g_zb[DHW];

__device__ __forceinline__ u64 pack2(float lo, float hi) {
    u64 r; asm("mov.b64 %0,{%1,%2};" : "=l"(r) : "f"(lo), "f"(hi)); return r;
}
__device__ __forceinline__ void unpack2(u64 v, float& lo, float& hi) {
    asm("mov.b64 {%0,%1},%2;" : "=f"(lo), "=f"(hi) : "l"(v));
}
__device__ __forceinline__ u64 ffma2(u64 a, u64 b, u64 c) {
    u64 r; asm("fma.rn.f32x2 %0,%1,%2,%3;" : "=l"(r) : "l"(a), "l"(b), "l"(c)); return r;
}
__device__ __forceinline__ int mod3(int x) { int m = x % 3; return m < 0 ? m + 3 : m; }

// ---------------- K0: init ----------------
__global__ void k_init(const float* __restrict__ img, float* __restrict__ out) {
    int i = blockIdx.x * blockDim.x + threadIdx.x;
    if (i < DHW) {
        float v = img[i];
        g_t[i] = v;
        out[i] = v;
        g_p[i] = 0.f; g_q[i] = 0.f; g_s[i] = 0.f;
    }
}

// ---------------- K1: z = t + (sino - sum_d t)/D  (float4) ----------------
__global__ void k_z(const float* __restrict__ sino) {
    int hw4 = blockIdx.x * blockDim.x + threadIdx.x;
    if (hw4 >= HWSZ / 4) return;
    const float4* t4 = (const float4*)g_t;
    float4* z4 = (float4*)g_z;
    float4 sum = make_float4(0.f, 0.f, 0.f, 0.f);
    #pragma unroll 8
    for (int d = 0; d < DD; d++) {
        float4 v = t4[d * (HWSZ / 4) + hw4];
        sum.x += v.x; sum.y += v.y; sum.z += v.z; sum.w += v.w;
    }
    float4 sn = ((const float4*)sino)[hw4];
    float4 r = make_float4((sn.x - sum.x) * (1.f/DD), (sn.y - sum.y) * (1.f/DD),
                           (sn.z - sum.z) * (1.f/DD), (sn.w - sum.w) * (1.f/DD));
    #pragma unroll 8
    for (int d = 0; d < DD; d++) {
        float4 v = t4[d * (HWSZ / 4) + hw4];
        z4[d * (HWSZ / 4) + hw4] = make_float4(v.x + r.x, v.y + r.y, v.z + r.z, v.w + r.w);
    }
}

// ---------------- K2: fused sliding-window conv block ----------------
__global__ __launch_bounds__(256, 3) void k_conv(
    const float* __restrict__ W1g, const float* __restrict__ B1g,
    const float* __restrict__ W2g, const float* __restrict__ B2g,
    const float* __restrict__ ntx, const float* __restrict__ nty,
    const float* __restrict__ ntz, const float* __restrict__ nt,
    int casc)
{
    extern __shared__ char sm[];
    ulonglong2* sHA = (ulonglong2*)(sm + OFF_HA);   // hidden ch0-3 pairs, 3 planes
    ulonglong2* sHB = (ulonglong2*)(sm + OFF_HB);   // hidden ch4-7 pairs
    u64* sW1 = (u64*)(sm + OFF_W1);                 // [k*4+p]
    u64* sW2 = (u64*)(sm + OFF_W2);
    u64* sB1 = (u64*)(sm + OFF_B1);
    float* sIn = (float*)(sm + OFF_IN);             // 3 planes x 720
    float* sB2 = (float*)(sm + OFF_B2);

    const int tid = threadIdx.x;
    const int b = blockIdx.z;                       // 0=dx 1=dy 2=dz 3=z
    const int h0 = blockIdx.y * TH, w0 = blockIdx.x * TW;

    // pack weights into smem
    if (tid < 108) {
        int k = tid >> 2, p = tid & 3;
        sW1[tid] = pack2(W1g[b*216 + (2*p)*27 + k], W1g[b*216 + (2*p+1)*27 + k]);
    } else if (tid < 216) {
        int t = tid - 108; int k = t >> 2, p = t & 3;
        sW2[t] = pack2(W2g[b*216 + (2*p)*27 + k], W2g[b*216 + (2*p+1)*27 + k]);
    } else if (tid < 220) {
        int p = tid - 216;
        sB1[p] = pack2(B1g[b*8 + 2*p], B1g[b*8 + 2*p + 1]);
    } else if (tid == 220) {
        sB2[0] = B2g[b];
    }
    const float eta = ((b == 0) ? ntx : (b == 1) ? nty : (b == 2) ? ntz : nt)[casc];
    const float* oldv = (b == 0) ? g_p : (b == 1) ? g_q : (b == 2) ? g_s : g_t;
    float*       dst  = (b == 0) ? g_p : (b == 1) ? g_q : (b == 2) ? g_s : g_zb;

    // ---- fill one input plane (depth id) computing diff on the fly ----
    auto fill_in = [&](int id) {
        float* dp = sIn + mod3(id) * NINP;
        for (int i = tid; i < NINP; i += 256) {
            int lh = i / IWP, lw = i - lh * IWP;
            int gh = h0 + lh - 2, gw = w0 + lw - 2;
            float v = 0.f;
            if (id >= 0 && id < DD && gh >= 0 && gh < HH_ && gw >= 0 && gw < WW) {
                const float* zp = g_z + ((size_t)id * HH_ + gh) * WW + gw;
                if (b == 3) v = zp[0];
                else if (b == 0) { if (gw < WW - 1) v = zp[1] - zp[0]; }
                else if (b == 1) { if (gh < HH_ - 1) v = zp[WW] - zp[0]; }
                else             { if (id < DD - 1) v = zp[HWSZ] - zp[0]; }
            }
            dp[i] = v;
        }
    };

    // ---- compute hidden plane hd (conv1 + relu), packed f32x2 ----
    auto comp_hid = [&](int hd) {
        int hs = mod3(hd);
        ulonglong2* HA = sHA + hs * NHP;
        ulonglong2* HB = sHB + hs * NHP;
        if (hd < 0 || hd >= DD) {
            for (int i = tid; i < NHP; i += 256) {
                HA[i] = make_ulonglong2(0ULL, 0ULL);
                HB[i] = make_ulonglong2(0ULL, 0ULL);
            }
            return;
        }
        const float* ips[3] = { sIn + mod3(hd - 1) * NINP,
                                sIn + mod3(hd)     * NINP,
                                sIn + mod3(hd + 1) * NINP };
        u64 acc[3][4];
        int base[3], idx[3];
        bool ok[3];
        #pragma unroll
        for (int j = 0; j < 3; j++) {
            int i = tid + j * 256;
            idx[j] = i;
            int ic = (i < NHP) ? i : 0;
            int hh = ic / HWP, hw = ic - hh * HWP;
            int gh = h0 + hh - 1, gw = w0 + hw - 1;
            ok[j] = (i < NHP) && gh >= 0 && gh < HH_ && gw >= 0 && gw < WW;
            base[j] = hh * IWP + hw;
            #pragma unroll
            for (int p = 0; p < 4; p++) acc[j][p] = sB1[p];
        }
        #pragma unroll
        for (int kd = 0; kd < 3; kd++) {
            const float* ip = ips[kd];
            #pragma unroll
            for (int kh = 0; kh < 3; kh++)
            #pragma unroll
            for (int kw = 0; kw < 3; kw++) {
                int k = kd * 9 + kh * 3 + kw;
                u64 wA = sW1[k*4+0], wB = sW1[k*4+1], wC = sW1[k*4+2], wD = sW1[k*4+3];
                int off = kh * IWP + kw;
                #pragma unroll
                for (int j = 0; j < 3; j++) {
                    float v = ip[base[j] + off];
                    u64 vv = pack2(v, v);
                    acc[j][0] = ffma2(wA, vv, acc[j][0]);
                    acc[j][1] = ffma2(wB, vv, acc[j][1]);
                    acc[j][2] = ffma2(wC, vv, acc[j][2]);
                    acc[j][3] = ffma2(wD, vv, acc[j][3]);
                }
            }
        }
        #pragma unroll
        for (int j = 0; j < 3; j++) {
            if (idx[j] < NHP) {
                u64 r[4];
                #pragma unroll
                for (int p = 0; p < 4; p++) {
                    float a, c; unpack2(acc[j][p], a, c);
                    r[p] = ok[j] ? pack2(fmaxf(a, 0.f), fmaxf(c, 0.f)) : 0ULL;
                }
                HA[idx[j]] = make_ulonglong2(r[0], r[1]);
                HB[idx[j]] = make_ulonglong2(r[2], r[3]);
            }
        }
    };

    // ---- conv2 + momentum update for output plane od ----
    auto do_out = [&](int od) {
        int ow = tid & 31, ohA = tid >> 5;        // outputs (ohA, ow) and (ohA+8, ow)
        const ulonglong2* HAs[3] = { sHA + mod3(od-1)*NHP, sHA + mod3(od)*NHP, sHA + mod3(od+1)*NHP };
        const ulonglong2* HBs[3] = { sHB + mod3(od-1)*NHP, sHB + mod3(od)*NHP, sHB + mod3(od+1)*NHP };
        u64 acc[2][4];
        #pragma unroll
        for (int o = 0; o < 2; o++)
            #pragma unroll
            for (int p = 0; p < 4; p++) acc[o][p] = 0ULL;
        #pragma unroll
        for (int kd = 0; kd < 3; kd++) {
            const ulonglong2* HA = HAs[kd];
            const ulonglong2* HB = HBs[kd];
            #pragma unroll
            for (int kh = 0; kh < 3; kh++)
            #pragma unroll
            for (int kw = 0; kw < 3; kw++) {
                int k = kd * 9 + kh * 3 + kw;
                u64 wA = sW2[k*4+0], wB = sW2[k*4+1], wC = sW2[k*4+2], wD = sW2[k*4+3];
                int hrow = kh * HWP + ow + kw;
                #pragma unroll
                for (int o = 0; o < 2; o++) {
                    int idx = (ohA + o * 8) * HWP + hrow;
                    ulonglong2 a = HA[idx];
                    ulonglong2 c = HB[idx];
                    acc[o][0] = ffma2(wA, a.x, acc[o][0]);
                    acc[o][1] = ffma2(wB, a.y, acc[o][1]);
                    acc[o][2] = ffma2(wC, c.x, acc[o][2]);
                    acc[o][3] = ffma2(wD, c.y, acc[o][3]);
                }
            }
        }
        float bb = sB2[0];
        #pragma unroll
        for (int o = 0; o < 2; o++) {
            float s = bb;
            #pragma unroll
            for (int p = 0; p < 4; p++) {
                float a, c; unpack2(acc[o][p], a, c);
                s += a + c;
            }
            int oh = ohA + o * 8;
            size_t gi = ((size_t)od * HH_ + (h0 + oh)) * WW + (w0 + ow);
            float old = oldv[gi];
            dst[gi] = old + eta * (old - s);
        }
    };

    // ---- prologue ----
    fill_in(-1); fill_in(0); fill_in(1);
    comp_hid(-1);                 // pure zero-store, no sIn reads
    __syncthreads();              // fills + weights visible
    comp_hid(0);

    // ---- main sliding loop ----
    for (int od = 0; od < DD; od++) {
        __syncthreads();          // prev hid-compute / conv2 reads done
        fill_in(od + 2);
        __syncthreads();          // fill visible
        comp_hid(od + 1);
        __syncthreads();          // hidden visible
        do_out(od);
    }
}

// ---------------- K3: t = divT(p,q,s) + z_ ; write output slice ----------------
__global__ void k_tupd(float* __restrict__ out, int casc) {
    int i = blockIdx.x * blockDim.x + threadIdx.x;
    if (i >= DHW) return;
    int w = i & (WW - 1);
    int h = (i >> 8) & (HH_ - 1);
    int d = i >> 16;
    float v = g_zb[i];
    v += ((w > 0) ? g_p[i - 1]    : 0.f) - ((w < WW - 1) ? g_p[i] : 0.f);
    v += ((h > 0) ? g_q[i - WW]   : 0.f) - ((h < HH_ - 1) ? g_q[i] : 0.f);
    v += ((d > 0) ? g_s[i - HWSZ] : 0.f) - ((d < DD - 1) ? g_s[i] : 0.f);
    g_t[i] = v;
    out[(casc + 1) * DHW + i] = v;
}

extern "C" void kernel_launch(void* const* d_in, const int* in_sizes, int n_in,
                              void* d_out, int out_size) {
    const float* image = (const float*)d_in[0];
    const float* sino  = (const float*)d_in[1];
    const float* W1    = (const float*)d_in[2];
    const float* B1    = (const float*)d_in[3];
    const float* W2    = (const float*)d_in[4];
    const float* B2    = (const float*)d_in[5];
    const float* ntx   = (const float*)d_in[6];
    const float* nty   = (const float*)d_in[7];
    const float* ntz   = (const float*)d_in[8];
    const float* nt    = (const float*)d_in[9];
    float* out = (float*)d_out;

    cudaFuncSetAttribute((const void*)k_conv,
                         cudaFuncAttributeMaxDynamicSharedMemorySize, SMEM_BYTES);

    k_init<<<DHW / 256, 256>>>(image, out);
    for (int c = 0; c < CASC; c++) {
        k_z<<<(HWSZ / 4) / 256, 256>>>(sino);
        dim3 grid(WW / TW, HH_ / TH, 4);   // (8, 16, 4) = 512 CTAs
        k_conv<<<grid, 256, SMEM_BYTES>>>(W1, B1, W2, B2, ntx, nty, ntz, nt, c);
        k_tupd<<<DHW / 256, 256>>>(out, c);
    }
}

// round 4
// speedup vs baseline: 2.6117x; 1.1822x over previous
#include <cuda_runtime.h>

#define DD 64
#define HH_ 256
#define WW 256
#define HWSZ 65536
#define DHW 4194304
#define CASC 3

#define TH 16
#define TW 32
#define IWP 38              // padded input row stride (36 used + 2 overread pad)
#define IHP 20
#define NINP (IHP*IWP)      // 760
#define HHP 18
#define HWP 34
#define NHP (HHP*HWP)       // 612

// smem byte offsets
#define OFF_HA 0                       // 4 planes x 612 x 16B
#define OFF_HB (OFF_HA + 4*NHP*16)     // 39168
#define OFF_IN (OFF_HB + 4*NHP*16)     // 78336 ; 4 planes x 760 x 4B
#define OFF_W1 (OFF_IN + 4*NINP*4)     // 90496
#define OFF_W2 (OFF_W1 + 27*32)        // 91360
#define OFF_B1 (OFF_W2 + 27*32)        // 92224
#define OFF_B2 (OFF_B1 + 32)           // 92256
#define SMEM_BYTES (OFF_B2 + 16)       // 92272

typedef unsigned long long u64;

__device__ float g_t[DHW];
__device__ float g_z[DHW];
__device__ float g_p[DHW];
__device__ float g_q[DHW];
__device__ float g_s[DHW];
__device__ float g_zb[DHW];

__device__ __forceinline__ u64 pack2(float lo, float hi) {
    u64 r; asm("mov.b64 %0,{%1,%2};" : "=l"(r) : "f"(lo), "f"(hi)); return r;
}
__device__ __forceinline__ void unpack2(u64 v, float& lo, float& hi) {
    asm("mov.b64 {%0,%1},%2;" : "=f"(lo), "=f"(hi) : "l"(v));
}
__device__ __forceinline__ u64 ffma2(u64 a, u64 b, u64 c) {
    u64 r; asm("fma.rn.f32x2 %0,%1,%2,%3;" : "=l"(r) : "l"(a), "l"(b), "l"(c)); return r;
}

// ---------------- K0: init ----------------
__global__ void k_init(const float* __restrict__ img, float* __restrict__ out) {
    int i = blockIdx.x * blockDim.x + threadIdx.x;
    if (i < DHW) {
        float v = img[i];
        g_t[i] = v;
        out[i] = v;
        g_p[i] = 0.f; g_q[i] = 0.f; g_s[i] = 0.f;
    }
}

// ---------------- K1: z = t + (sino - sum_d t)/D  (float4) ----------------
__global__ void k_z(const float* __restrict__ sino) {
    int hw4 = blockIdx.x * blockDim.x + threadIdx.x;
    if (hw4 >= HWSZ / 4) return;
    const float4* t4 = (const float4*)g_t;
    float4* z4 = (float4*)g_z;
    float4 sum = make_float4(0.f, 0.f, 0.f, 0.f);
    #pragma unroll 8
    for (int d = 0; d < DD; d++) {
        float4 v = t4[d * (HWSZ / 4) + hw4];
        sum.x += v.x; sum.y += v.y; sum.z += v.z; sum.w += v.w;
    }
    float4 sn = ((const float4*)sino)[hw4];
    float4 r = make_float4((sn.x - sum.x) * (1.f/DD), (sn.y - sum.y) * (1.f/DD),
                           (sn.z - sum.z) * (1.f/DD), (sn.w - sum.w) * (1.f/DD));
    #pragma unroll 8
    for (int d = 0; d < DD; d++) {
        float4 v = t4[d * (HWSZ / 4) + hw4];
        z4[d * (HWSZ / 4) + hw4] = make_float4(v.x + r.x, v.y + r.y, v.z + r.z, v.w + r.w);
    }
}

// ---------------- K2: fused sliding-window conv block, 2 planes/step ----------------
__global__ __launch_bounds__(256, 2) void k_conv(
    const float* __restrict__ W1g, const float* __restrict__ B1g,
    const float* __restrict__ W2g, const float* __restrict__ B2g,
    const float* __restrict__ ntx, const float* __restrict__ nty,
    const float* __restrict__ ntz, const float* __restrict__ nt,
    int casc)
{
    extern __shared__ char sm[];
    ulonglong2* sHA = (ulonglong2*)(sm + OFF_HA);   // ch0-3 pairs, 4 planes
    ulonglong2* sHB = (ulonglong2*)(sm + OFF_HB);   // ch4-7 pairs
    float* sIn = (float*)(sm + OFF_IN);             // 4 planes x NINP
    u64* sW1u = (u64*)(sm + OFF_W1);                // [k*4+q]
    u64* sW2u = (u64*)(sm + OFF_W2);
    u64* sB1 = (u64*)(sm + OFF_B1);
    float* sB2 = (float*)(sm + OFF_B2);
    const ulonglong2* sW1v = (const ulonglong2*)sW1u;  // [k*2+i]
    const ulonglong2* sW2v = (const ulonglong2*)sW2u;

    const int tid = threadIdx.x;
    const int b = blockIdx.z;                       // 0=dx 1=dy 2=dz 3=z
    const int h0 = blockIdx.y * TH, w0 = blockIdx.x * TW;

    if (tid < 108) {
        int k = tid >> 2, q = tid & 3;
        sW1u[k * 4 + q] = pack2(W1g[b*216 + (2*q)*27 + k], W1g[b*216 + (2*q+1)*27 + k]);
    } else if (tid < 216) {
        int t = tid - 108; int k = t >> 2, q = t & 3;
        sW2u[k * 4 + q] = pack2(W2g[b*216 + (2*q)*27 + k], W2g[b*216 + (2*q+1)*27 + k]);
    } else if (tid < 220) {
        int q = tid - 216;
        sB1[q] = pack2(B1g[b*8 + 2*q], B1g[b*8 + 2*q + 1]);
    } else if (tid == 220) {
        sB2[0] = B2g[b];
    }
    const float eta = ((b == 0) ? ntx : (b == 1) ? nty : (b == 2) ? ntz : nt)[casc];
    const float* oldv = (b == 0) ? g_p : (b == 1) ? g_q : (b == 2) ? g_s : g_t;
    float*       dst  = (b == 0) ? g_p : (b == 1) ? g_q : (b == 2) ? g_s : g_zb;

    // ---- fill one input plane (depth id), diff computed on the fly ----
    auto fill_in = [&](int id) {
        float* dp = sIn + (id & 3) * NINP;
        for (int i = tid; i < 720; i += 256) {
            int lh = i / 36, lw = i - lh * 36;
            int gh = h0 + lh - 2, gw = w0 + lw - 2;
            float v = 0.f;
            if (id >= 0 && id < DD && gh >= 0 && gh < HH_ && gw >= 0 && gw < WW) {
                const float* zp = g_z + ((size_t)id * HH_ + gh) * WW + gw;
                if (b == 3) v = zp[0];
                else if (b == 0) { if (gw < WW - 1) v = zp[1] - zp[0]; }
                else if (b == 1) { if (gh < HH_ - 1) v = zp[WW] - zp[0]; }
                else             { if (id < DD - 1) v = zp[HWSZ] - zp[0]; }
            }
            dp[lh * IWP + lw] = v;
        }
    };

    // ---- conv1+relu for hidden planes hd1, hd2 (hd2 == hd1+1) ----
    auto comp_pair = [&](int hd1) {
        const int hd2 = hd1 + 1;
        const bool v1 = (hd1 >= 0 && hd1 < DD);
        const bool v2 = (hd2 >= 0 && hd2 < DD);
        ulonglong2* HA1 = sHA + (hd1 & 3) * NHP;
        ulonglong2* HB1 = sHB + (hd1 & 3) * NHP;
        ulonglong2* HA2 = sHA + (hd2 & 3) * NHP;
        ulonglong2* HB2 = sHB + (hd2 & 3) * NHP;
        if (tid >= 216) return;
        const int r = tid / 12, seg = tid - 12 * r;
        const int hw0 = seg * 3;
        u64 acc1[3][4], acc2[3][4];
        #pragma unroll
        for (int j = 0; j < 3; j++)
            #pragma unroll
            for (int q = 0; q < 4; q++) { acc1[j][q] = sB1[q]; acc2[j][q] = sB1[q]; }
        #pragma unroll
        for (int kd = 0; kd < 3; kd++) {
            const float* p1 = sIn + ((hd1 - 1 + kd) & 3) * NINP;
            const float* p2 = sIn + ((hd2 - 1 + kd) & 3) * NINP;
            #pragma unroll
            for (int kh = 0; kh < 3; kh++) {
                int ro = (r + kh) * IWP + hw0;
                u64 va[5], vb[5];
                #pragma unroll
                for (int m = 0; m < 5; m++) {
                    float a = p1[ro + m], c = p2[ro + m];
                    va[m] = pack2(a, a);
                    vb[m] = pack2(c, c);
                }
                #pragma unroll
                for (int kw = 0; kw < 3; kw++) {
                    int k = kd * 9 + kh * 3 + kw;
                    ulonglong2 wA = sW1v[k * 2], wB = sW1v[k * 2 + 1];
                    #pragma unroll
                    for (int j = 0; j < 3; j++) {
                        acc1[j][0] = ffma2(wA.x, va[j + kw], acc1[j][0]);
                        acc1[j][1] = ffma2(wA.y, va[j + kw], acc1[j][1]);
                        acc1[j][2] = ffma2(wB.x, va[j + kw], acc1[j][2]);
                        acc1[j][3] = ffma2(wB.y, va[j + kw], acc1[j][3]);
                        acc2[j][0] = ffma2(wA.x, vb[j + kw], acc2[j][0]);
                        acc2[j][1] = ffma2(wA.y, vb[j + kw], acc2[j][1]);
                        acc2[j][2] = ffma2(wB.x, vb[j + kw], acc2[j][2]);
                        acc2[j][3] = ffma2(wB.y, vb[j + kw], acc2[j][3]);
                    }
                }
            }
        }
        #pragma unroll
        for (int j = 0; j < 3; j++) {
            int hw = hw0 + j;
            if (hw >= HWP) continue;
            int gh = h0 + r - 1, gw = w0 + hw - 1;
            bool okxy = (gh >= 0 && gh < HH_ && gw >= 0 && gw < WW);
            int idx = r * HWP + hw;
            u64 r1[4], r2[4];
            #pragma unroll
            for (int q = 0; q < 4; q++) {
                float a, c;
                unpack2(acc1[j][q], a, c);
                r1[q] = (okxy && v1) ? pack2(fmaxf(a, 0.f), fmaxf(c, 0.f)) : 0ULL;
                unpack2(acc2[j][q], a, c);
                r2[q] = (okxy && v2) ? pack2(fmaxf(a, 0.f), fmaxf(c, 0.f)) : 0ULL;
            }
            HA1[idx] = make_ulonglong2(r1[0], r1[1]);
            HB1[idx] = make_ulonglong2(r1[2], r1[3]);
            HA2[idx] = make_ulonglong2(r2[0], r2[1]);
            HB2[idx] = make_ulonglong2(r2[2], r2[3]);
        }
    };

    // ---- conv2 + momentum update for output planes od, od+1 ----
    auto do_out2 = [&](int od) {
        const int ow = tid & 31, ohA = tid >> 5;     // rows ohA and ohA+8
        const ulonglong2* HAp[4]; const ulonglong2* HBp[4];
        #pragma unroll
        for (int pp = 0; pp < 4; pp++) {
            HAp[pp] = sHA + ((od - 1 + pp) & 3) * NHP;
            HBp[pp] = sHB + ((od - 1 + pp) & 3) * NHP;
        }
        u64 acc[2][2][4];                            // [odsel][o][pair]
        #pragma unroll
        for (int s = 0; s < 2; s++)
            #pragma unroll
            for (int o = 0; o < 2; o++)
                #pragma unroll
                for (int q = 0; q < 4; q++) acc[s][o][q] = 0ULL;
        #pragma unroll
        for (int kh = 0; kh < 3; kh++)
        #pragma unroll
        for (int kw = 0; kw < 3; kw++) {
            ulonglong2 w[3][2];
            #pragma unroll
            for (int kd = 0; kd < 3; kd++) {
                int k = kd * 9 + kh * 3 + kw;
                w[kd][0] = sW2v[k * 2];
                w[kd][1] = sW2v[k * 2 + 1];
            }
            #pragma unroll
            for (int o = 0; o < 2; o++) {
                int idx = (ohA + o * 8 + kh) * HWP + ow + kw;
                #pragma unroll
                for (int pp = 0; pp < 4; pp++) {
                    ulonglong2 hA = HAp[pp][idx];
                    ulonglong2 hB = HBp[pp][idx];
                    if (pp < 3) {
                        acc[0][o][0] = ffma2(w[pp][0].x, hA.x, acc[0][o][0]);
                        acc[0][o][1] = ffma2(w[pp][0].y, hA.y, acc[0][o][1]);
                        acc[0][o][2] = ffma2(w[pp][1].x, hB.x, acc[0][o][2]);
                        acc[0][o][3] = ffma2(w[pp][1].y, hB.y, acc[0][o][3]);
                    }
                    if (pp > 0) {
                        acc[1][o][0] = ffma2(w[pp-1][0].x, hA.x, acc[1][o][0]);
                        acc[1][o][1] = ffma2(w[pp-1][0].y, hA.y, acc[1][o][1]);
                        acc[1][o][2] = ffma2(w[pp-1][1].x, hB.x, acc[1][o][2]);
                        acc[1][o][3] = ffma2(w[pp-1][1].y, hB.y, acc[1][o][3]);
                    }
                }
            }
        }
        float bb = sB2[0];
        #pragma unroll
        for (int s = 0; s < 2; s++)
        #pragma unroll
        for (int o = 0; o < 2; o++) {
            float sum = bb;
            #pragma unroll
            for (int q = 0; q < 4; q++) {
                float a, c; unpack2(acc[s][o][q], a, c);
                sum += a + c;
            }
            int oh = ohA + o * 8;
            size_t gi = ((size_t)(od + s) * HH_ + (h0 + oh)) * WW + (w0 + ow);
            float old = oldv[gi];
            dst[gi] = old + eta * (old - sum);
        }
    };

    // ---- prologue ----
    fill_in(-1); fill_in(0); fill_in(1);
    __syncthreads();
    comp_pair(-1);          // hidden -1 (zeros) and 0

    // ---- main loop, 2 planes per step ----
    for (int od = 0; od < DD; od += 2) {
        __syncthreads();
        fill_in(od + 2); fill_in(od + 3);
        __syncthreads();
        comp_pair(od + 1);  // hidden od+1, od+2
        __syncthreads();
        do_out2(od);
    }
}

// ---------------- K3: t = divT(p,q,s) + z_ ; write output slice ----------------
__global__ void k_tupd(float* __restrict__ out, int casc) {
    int i = blockIdx.x * blockDim.x + threadIdx.x;
    if (i >= DHW) return;
    int w = i & (WW - 1);
    int h = (i >> 8) & (HH_ - 1);
    int d = i >> 16;
    float v = g_zb[i];
    v += ((w > 0) ? g_p[i - 1]    : 0.f) - ((w < WW - 1) ? g_p[i] : 0.f);
    v += ((h > 0) ? g_q[i - WW]   : 0.f) - ((h < HH_ - 1) ? g_q[i] : 0.f);
    v += ((d > 0) ? g_s[i - HWSZ] : 0.f) - ((d < DD - 1) ? g_s[i] : 0.f);
    g_t[i] = v;
    out[(casc + 1) * DHW + i] = v;
}

extern "C" void kernel_launch(void* const* d_in, const int* in_sizes, int n_in,
                              void* d_out, int out_size) {
    const float* image = (const float*)d_in[0];
    const float* sino  = (const float*)d_in[1];
    const float* W1    = (const float*)d_in[2];
    const float* B1    = (const float*)d_in[3];
    const float* W2    = (const float*)d_in[4];
    const float* B2    = (const float*)d_in[5];
    const float* ntx   = (const float*)d_in[6];
    const float* nty   = (const float*)d_in[7];
    const float* ntz   = (const float*)d_in[8];
    const float* nt    = (const float*)d_in[9];
    float* out = (float*)d_out;

    cudaFuncSetAttribute((const void*)k_conv,
                         cudaFuncAttributeMaxDynamicSharedMemorySize, SMEM_BYTES);

    k_init<<<DHW / 256, 256>>>(image, out);
    for (int c = 0; c < CASC; c++) {
        k_z<<<(HWSZ / 4) / 256, 256>>>(sino);
        dim3 grid(WW / TW, HH_ / TH, 4);   // 512 CTAs
        k_conv<<<grid, 256, SMEM_BYTES>>>(W1, B1, W2, B2, ntx, nty, ntz, nt, c);
        k_tupd<<<DHW / 256, 256>>>(out, c);
    }
}

// round 6
// speedup vs baseline: 2.9980x; 1.1479x over previous
#include <cuda_runtime.h>

#define DD 64
#define HH_ 256
#define WW 256
#define HWSZ 65536
#define DHW 4194304
#define CASC 3

#define TH 16
#define TW 32
#define IWP 38              // padded input row stride
#define IHP 20
#define NINP (IHP*IWP)      // 760
#define HHP 18
#define HWP 34
#define NHP (HHP*HWP)       // 612

// smem byte offsets
#define OFF_HA 0                       // 4 planes x 612 x 16B
#define OFF_HB (OFF_HA + 4*NHP*16)     // 39168
#define OFF_IN (OFF_HB + 4*NHP*16)     // 78336 ; 4 planes x 760 x 4B
#define OFF_W1 (OFF_IN + 4*NINP*4)     // 90496
#define OFF_W2 (OFF_W1 + 27*32)        // 91360
#define OFF_B1 (OFF_W2 + 27*32)        // 92224
#define OFF_B2 (OFF_B1 + 32)           // 92256
#define SMEM_BYTES (OFF_B2 + 16)       // 92272

typedef unsigned long long u64;

__device__ float g_t[DHW];
__device__ float g_z[DHW];
__device__ float g_p[DHW];
__device__ float g_q[DHW];
__device__ float g_s[DHW];
__device__ float g_zb[DHW];

__device__ __forceinline__ u64 pack2(float lo, float hi) {
    u64 r; asm("mov.b64 %0,{%1,%2};" : "=l"(r) : "f"(lo), "f"(hi)); return r;
}
__device__ __forceinline__ void unpack2(u64 v, float& lo, float& hi) {
    asm("mov.b64 {%0,%1},%2;" : "=f"(lo), "=f"(hi) : "l"(v));
}
__device__ __forceinline__ u64 ffma2(u64 a, u64 b, u64 c) {
    u64 r; asm("fma.rn.f32x2 %0,%1,%2,%3;" : "=l"(r) : "l"(a), "l"(b), "l"(c)); return r;
}

// ---------------- K0: init (float4) ----------------
__global__ void k_init(const float* __restrict__ img, float* __restrict__ out) {
    int i4 = blockIdx.x * blockDim.x + threadIdx.x;
    if (i4 < DHW / 4) {
        float4 v = ((const float4*)img)[i4];
        ((float4*)g_t)[i4] = v;
        ((float4*)out)[i4] = v;
        float4 z = make_float4(0.f, 0.f, 0.f, 0.f);
        ((float4*)g_p)[i4] = z; ((float4*)g_q)[i4] = z; ((float4*)g_s)[i4] = z;
    }
}

// ---------------- K1: z = t + (sino - sum_d t)/D  (float4) ----------------
__global__ void k_z(const float* __restrict__ sino) {
    int hw4 = blockIdx.x * blockDim.x + threadIdx.x;
    if (hw4 >= HWSZ / 4) return;
    const float4* t4 = (const float4*)g_t;
    float4* z4 = (float4*)g_z;
    float4 sum = make_float4(0.f, 0.f, 0.f, 0.f);
    #pragma unroll 8
    for (int d = 0; d < DD; d++) {
        float4 v = t4[d * (HWSZ / 4) + hw4];
        sum.x += v.x; sum.y += v.y; sum.z += v.z; sum.w += v.w;
    }
    float4 sn = ((const float4*)sino)[hw4];
    float4 r = make_float4((sn.x - sum.x) * (1.f/DD), (sn.y - sum.y) * (1.f/DD),
                           (sn.z - sum.z) * (1.f/DD), (sn.w - sum.w) * (1.f/DD));
    #pragma unroll 8
    for (int d = 0; d < DD; d++) {
        float4 v = t4[d * (HWSZ / 4) + hw4];
        z4[d * (HWSZ / 4) + hw4] = make_float4(v.x + r.x, v.y + r.y, v.z + r.z, v.w + r.w);
    }
}

// ---------------- K2: fused sliding-window conv block, 2 planes/step, pipelined ----------------
__global__ __launch_bounds__(256, 2) void k_conv(
    const float* __restrict__ W1g, const float* __restrict__ B1g,
    const float* __restrict__ W2g, const float* __restrict__ B2g,
    const float* __restrict__ ntx, const float* __restrict__ nty,
    const float* __restrict__ ntz, const float* __restrict__ nt,
    int casc)
{
    extern __shared__ char sm[];
    ulonglong2* sHA = (ulonglong2*)(sm + OFF_HA);
    ulonglong2* sHB = (ulonglong2*)(sm + OFF_HB);
    float* sIn = (float*)(sm + OFF_IN);
    u64* sW1u = (u64*)(sm + OFF_W1);
    u64* sW2u = (u64*)(sm + OFF_W2);
    u64* sB1 = (u64*)(sm + OFF_B1);
    float* sB2 = (float*)(sm + OFF_B2);
    const ulonglong2* sW1v = (const ulonglong2*)sW1u;
    const ulonglong2* sW2v = (const ulonglong2*)sW2u;

    const int tid = threadIdx.x;
    const int b = blockIdx.z;                       // 0=dx 1=dy 2=dz 3=z
    const int h0 = blockIdx.y * TH, w0 = blockIdx.x * TW;

    if (tid < 108) {
        int k = tid >> 2, q = tid & 3;
        sW1u[k * 4 + q] = pack2(W1g[b*216 + (2*q)*27 + k], W1g[b*216 + (2*q+1)*27 + k]);
    } else if (tid < 216) {
        int t = tid - 108; int k = t >> 2, q = t & 3;
        sW2u[k * 4 + q] = pack2(W2g[b*216 + (2*q)*27 + k], W2g[b*216 + (2*q+1)*27 + k]);
    } else if (tid < 220) {
        int q = tid - 216;
        sB1[q] = pack2(B1g[b*8 + 2*q], B1g[b*8 + 2*q + 1]);
    } else if (tid == 220) {
        sB2[0] = B2g[b];
    }
    const float eta = ((b == 0) ? ntx : (b == 1) ? nty : (b == 2) ? ntz : nt)[casc];
    const float* oldv = (b == 0) ? g_p : (b == 1) ? g_q : (b == 2) ? g_s : g_t;
    float*       dst  = (b == 0) ? g_p : (b == 1) ? g_q : (b == 2) ? g_s : g_zb;

    // per-thread element coords for plane fill (3 elems per plane)
    auto load_elem = [&](int id, int j) -> float {
        int i = tid + j * 256;
        if (i >= 720) return 0.f;
        int lh = i / 36, lw = i - lh * 36;
        int gh = h0 + lh - 2, gw = w0 + lw - 2;
        float v = 0.f;
        if (id >= 0 && id < DD && gh >= 0 && gh < HH_ && gw >= 0 && gw < WW) {
            const float* zp = g_z + ((size_t)id * HH_ + gh) * WW + gw;
            if (b == 3) v = zp[0];
            else if (b == 0) { if (gw < WW - 1) v = zp[1] - zp[0]; }
            else if (b == 1) { if (gh < HH_ - 1) v = zp[WW] - zp[0]; }
            else             { if (id < DD - 1) v = zp[HWSZ] - zp[0]; }
        }
        return v;
    };
    auto pre_load = [&](int id, float* R) {
        #pragma unroll
        for (int j = 0; j < 3; j++) R[j] = load_elem(id, j);
    };
    auto sts_plane = [&](int id, const float* R) {
        float* dp = sIn + (id & 3) * NINP;
        #pragma unroll
        for (int j = 0; j < 3; j++) {
            int i = tid + j * 256;
            if (i < 720) {
                int lh = i / 36, lw = i - lh * 36;
                dp[lh * IWP + lw] = R[j];
            }
        }
    };
    auto fill_in = [&](int id) {
        float R[3]; pre_load(id, R); sts_plane(id, R);
    };

    // ---- conv1+relu for hidden planes hd1, hd1+1 ----
    auto comp_pair = [&](int hd1) {
        const int hd2 = hd1 + 1;
        const bool v1 = (hd1 >= 0 && hd1 < DD);
        const bool v2 = (hd2 >= 0 && hd2 < DD);
        ulonglong2* HA1 = sHA + (hd1 & 3) * NHP;
        ulonglong2* HB1 = sHB + (hd1 & 3) * NHP;
        ulonglong2* HA2 = sHA + (hd2 & 3) * NHP;
        ulonglong2* HB2 = sHB + (hd2 & 3) * NHP;
        if (tid >= 216) return;
        const int r = tid / 12, seg = tid - 12 * r;
        const int hw0 = seg * 3;
        u64 acc1[3][4], acc2[3][4];
        #pragma unroll
        for (int j = 0; j < 3; j++)
            #pragma unroll
            for (int q = 0; q < 4; q++) { acc1[j][q] = sB1[q]; acc2[j][q] = sB1[q]; }
        #pragma unroll
        for (int kd = 0; kd < 3; kd++) {
            const float* p1 = sIn + ((hd1 - 1 + kd) & 3) * NINP;
            const float* p2 = sIn + ((hd2 - 1 + kd) & 3) * NINP;
            #pragma unroll
            for (int kh = 0; kh < 3; kh++) {
                int ro = (r + kh) * IWP + hw0;
                u64 va[5], vb[5];
                #pragma unroll
                for (int m = 0; m < 5; m++) {
                    float a = p1[ro + m], c = p2[ro + m];
                    va[m] = pack2(a, a);
                    vb[m] = pack2(c, c);
                }
                #pragma unroll
                for (int kw = 0; kw < 3; kw++) {
                    int k = kd * 9 + kh * 3 + kw;
                    ulonglong2 wA = sW1v[k * 2], wB = sW1v[k * 2 + 1];
                    #pragma unroll
                    for (int j = 0; j < 3; j++) {
                        acc1[j][0] = ffma2(wA.x, va[j + kw], acc1[j][0]);
                        acc1[j][1] = ffma2(wA.y, va[j + kw], acc1[j][1]);
                        acc1[j][2] = ffma2(wB.x, va[j + kw], acc1[j][2]);
                        acc1[j][3] = ffma2(wB.y, va[j + kw], acc1[j][3]);
                        acc2[j][0] = ffma2(wA.x, vb[j + kw], acc2[j][0]);
                        acc2[j][1] = ffma2(wA.y, vb[j + kw], acc2[j][1]);
                        acc2[j][2] = ffma2(wB.x, vb[j + kw], acc2[j][2]);
                        acc2[j][3] = ffma2(wB.y, vb[j + kw], acc2[j][3]);
                    }
                }
            }
        }
        #pragma unroll
        for (int j = 0; j < 3; j++) {
            int hw = hw0 + j;
            if (hw >= HWP) continue;
            int gh = h0 + r - 1, gw = w0 + hw - 1;
            bool okxy = (gh >= 0 && gh < HH_ && gw >= 0 && gw < WW);
            int idx = r * HWP + hw;
            u64 r1[4], r2[4];
            #pragma unroll
            for (int q = 0; q < 4; q++) {
                float a, c;
                unpack2(acc1[j][q], a, c);
                r1[q] = (okxy && v1) ? pack2(fmaxf(a, 0.f), fmaxf(c, 0.f)) : 0ULL;
                unpack2(acc2[j][q], a, c);
                r2[q] = (okxy && v2) ? pack2(fmaxf(a, 0.f), fmaxf(c, 0.f)) : 0ULL;
            }
            HA1[idx] = make_ulonglong2(r1[0], r1[1]);
            HB1[idx] = make_ulonglong2(r1[2], r1[3]);
            HA2[idx] = make_ulonglong2(r2[0], r2[1]);
            HB2[idx] = make_ulonglong2(r2[2], r2[3]);
        }
    };

    // ---- conv2 + momentum update for output planes od, od+1 ----
    auto do_out2 = [&](int od) {
        const int ow = tid & 31, ohA = tid >> 5;
        const ulonglong2* HAp[4]; const ulonglong2* HBp[4];
        #pragma unroll
        for (int pp = 0; pp < 4; pp++) {
            HAp[pp] = sHA + ((od - 1 + pp) & 3) * NHP;
            HBp[pp] = sHB + ((od - 1 + pp) & 3) * NHP;
        }
        u64 acc[2][2][4];
        #pragma unroll
        for (int s = 0; s < 2; s++)
            #pragma unroll
            for (int o = 0; o < 2; o++)
                #pragma unroll
                for (int q = 0; q < 4; q++) acc[s][o][q] = 0ULL;
        #pragma unroll
        for (int kh = 0; kh < 3; kh++)
        #pragma unroll
        for (int kw = 0; kw < 3; kw++) {
            ulonglong2 w[3][2];
            #pragma unroll
            for (int kd = 0; kd < 3; kd++) {
                int k = kd * 9 + kh * 3 + kw;
                w[kd][0] = sW2v[k * 2];
                w[kd][1] = sW2v[k * 2 + 1];
            }
            #pragma unroll
            for (int o = 0; o < 2; o++) {
                int idx = (ohA + o * 8 + kh) * HWP + ow + kw;
                #pragma unroll
                for (int pp = 0; pp < 4; pp++) {
                    ulonglong2 hA = HAp[pp][idx];
                    ulonglong2 hB = HBp[pp][idx];
                    if (pp < 3) {
                        acc[0][o][0] = ffma2(w[pp][0].x, hA.x, acc[0][o][0]);
                        acc[0][o][1] = ffma2(w[pp][0].y, hA.y, acc[0][o][1]);
                        acc[0][o][2] = ffma2(w[pp][1].x, hB.x, acc[0][o][2]);
                        acc[0][o][3] = ffma2(w[pp][1].y, hB.y, acc[0][o][3]);
                    }
                    if (pp > 0) {
                        acc[1][o][0] = ffma2(w[pp-1][0].x, hA.x, acc[1][o][0]);
                        acc[1][o][1] = ffma2(w[pp-1][0].y, hA.y, acc[1][o][1]);
                        acc[1][o][2] = ffma2(w[pp-1][1].x, hB.x, acc[1][o][2]);
                        acc[1][o][3] = ffma2(w[pp-1][1].y, hB.y, acc[1][o][3]);
                    }
                }
            }
        }
        float bb = sB2[0];
        #pragma unroll
        for (int s = 0; s < 2; s++)
        #pragma unroll
        for (int o = 0; o < 2; o++) {
            float sum = bb;
            #pragma unroll
            for (int q = 0; q < 4; q++) {
                float a, c; unpack2(acc[s][o][q], a, c);
                sum += a + c;
            }
            int oh = ohA + o * 8;
            size_t gi = ((size_t)(od + s) * HH_ + (h0 + oh)) * WW + (w0 + ow);
            float old = oldv[gi];
            dst[gi] = old + eta * (old - sum);
        }
    };

    // ---- prologue ----
    fill_in(-1); fill_in(0); fill_in(1); fill_in(2);
    __syncthreads();
    comp_pair(-1);                 // hidden -1 (zeros), 0
    __syncthreads();
    float R[6];
    fill_in(3);                    // slot 3 (plane -1 already consumed)
    pre_load(4, R); pre_load(5, R + 3);
    __syncthreads();

    // ---- main loop: 2 barriers / 2 planes; LDG overlapped with compute ----
    for (int od = 0; od < DD; od += 2) {
        comp_pair(od + 1);          // hidden od+1, od+2 (reads input od..od+3)
        __syncthreads();
        sts_plane(od + 4, R);       // slots freed by comp_pair above
        sts_plane(od + 5, R + 3);
        pre_load(od + 6, R);        // LDG for next iteration, overlapped with do_out2
        pre_load(od + 7, R + 3);
        do_out2(od);                // reads hidden od-1..od+2
        __syncthreads();
    }
}

// ---------------- K3: t = divT(p,q,s) + z_ (float4) ----------------
__global__ void k_tupd(float* __restrict__ out, int casc) {
    int i4 = blockIdx.x * blockDim.x + threadIdx.x;
    if (i4 >= DHW / 4) return;
    int i = i4 * 4;
    int w = i & (WW - 1);
    int h = (i >> 8) & (HH_ - 1);
    int d = i >> 16;
    const float4* p4 = (const float4*)g_p;
    const float4* q4 = (const float4*)g_q;
    const float4* s4 = (const float4*)g_s;
    float4 v = ((const float4*)g_zb)[i4];
    // x-div
    float4 pc = p4[i4];
    float pm = (w > 0) ? g_p[i - 1] : 0.f;
    v.x += pm   - pc.x;
    v.y += pc.x - pc.y;
    v.z += pc.y - pc.z;
    v.w += pc.z - ((w + 3 < WW - 1) ? pc.w : 0.f);
    // y-div
    float4 qc = q4[i4];
    if (h < HH_ - 1) { v.x -= qc.x; v.y -= qc.y; v.z -= qc.z; v.w -= qc.w; }
    if (h > 0) {
        float4 qu = q4[i4 - WW / 4];
        v.x += qu.x; v.y += qu.y; v.z += qu.z; v.w += qu.w;
    }
    // z-div
    float4 sc = s4[i4];
    if (d < DD - 1) { v.x -= sc.x; v.y -= sc.y; v.z -= sc.z; v.w -= sc.w; }
    if (d > 0) {
        float4 su = s4[i4 - HWSZ / 4];
        v.x += su.x; v.y += su.y; v.z += su.z; v.w += su.w;
    }
    ((float4*)g_t)[i4] = v;
    ((float4*)(out + (size_t)(casc + 1) * DHW))[i4] = v;
}

extern "C" void kernel_launch(void* const* d_in, const int* in_sizes, int n_in,
                              void* d_out, int out_size) {
    const float* image = (const float*)d_in[0];
    const float* sino  = (const float*)d_in[1];
    const float* W1    = (const float*)d_in[2];
    const float* B1    = (const float*)d_in[3];
    const float* W2    = (const float*)d_in[4];
    const float* B2    = (const float*)d_in[5];
    const float* ntx   = (const float*)d_in[6];
    const float* nty   = (const float*)d_in[7];
    const float* ntz   = (const float*)d_in[8];
    const float* nt    = (const float*)d_in[9];
    float* out = (float*)d_out;

    cudaFuncSetAttribute((const void*)k_conv,
                         cudaFuncAttributeMaxDynamicSharedMemorySize, SMEM_BYTES);

    k_init<<<(DHW / 4) / 256, 256>>>(image, out);
    for (int c = 0; c < CASC; c++) {
        k_z<<<(HWSZ / 4) / 256, 256>>>(sino);
        dim3 grid(WW / TW, HH_ / TH, 4);   // 512 CTAs
        k_conv<<<grid, 256, SMEM_BYTES>>>(W1, B1, W2, B2, ntx, nty, ntz, nt, c);
        k_tupd<<<(DHW / 4) / 256, 256>>>(out, c);
    }
}

// round 7
// speedup vs baseline: 3.4354x; 1.1459x over previous
#include <cuda_runtime.h>

#define DD 64
#define HH_ 256
#define WW 256
#define HWSZ 65536
#define DHW 4194304
#define CASC 3

#define TH 16
#define TW 32
#define IWP 38              // padded input row stride
#define IHP 20
#define NINP (IHP*IWP)      // 760
#define HHP 18
#define HWP 34
#define NHP (HHP*HWP)       // 612
#define HROW 17             // parity-split row stride (slots)
#define HODD (HHP*HROW)     // 306 : offset of odd array within a plane

// smem byte offsets
#define OFF_HA 0                       // 4 planes x 612 x 16B
#define OFF_HB (OFF_HA + 4*NHP*16)     // 39168
#define OFF_IN (OFF_HB + 4*NHP*16)     // 78336 ; 4 planes x 760 x 4B
#define OFF_W1 (OFF_IN + 4*NINP*4)     // 90496
#define OFF_W2 (OFF_W1 + 27*32)        // 91360
#define OFF_B1 (OFF_W2 + 27*32)        // 92224
#define OFF_B2 (OFF_B1 + 32)           // 92256
#define SMEM_BYTES (OFF_B2 + 16)       // 92272

typedef unsigned long long u64;

__device__ float g_t[DHW];
__device__ float g_z[DHW];
__device__ float g_p[DHW];
__device__ float g_q[DHW];
__device__ float g_s[DHW];
__device__ float g_zb[DHW];

__device__ __forceinline__ u64 pack2(float lo, float hi) {
    u64 r; asm("mov.b64 %0,{%1,%2};" : "=l"(r) : "f"(lo), "f"(hi)); return r;
}
__device__ __forceinline__ void unpack2(u64 v, float& lo, float& hi) {
    asm("mov.b64 {%0,%1},%2;" : "=f"(lo), "=f"(hi) : "l"(v));
}
__device__ __forceinline__ u64 ffma2(u64 a, u64 b, u64 c) {
    u64 r; asm("fma.rn.f32x2 %0,%1,%2,%3;" : "=l"(r) : "l"(a), "l"(b), "l"(c)); return r;
}

// ---------------- K0: init (float4) ----------------
__global__ void k_init(const float* __restrict__ img, float* __restrict__ out) {
    int i4 = blockIdx.x * blockDim.x + threadIdx.x;
    if (i4 < DHW / 4) {
        float4 v = ((const float4*)img)[i4];
        ((float4*)g_t)[i4] = v;
        ((float4*)out)[i4] = v;
        float4 z = make_float4(0.f, 0.f, 0.f, 0.f);
        ((float4*)g_p)[i4] = z; ((float4*)g_q)[i4] = z; ((float4*)g_s)[i4] = z;
    }
}

// ---------------- K1: z = t + (sino - sum_d t)/D  (float4) ----------------
__global__ void k_z(const float* __restrict__ sino) {
    int hw4 = blockIdx.x * blockDim.x + threadIdx.x;
    if (hw4 >= HWSZ / 4) return;
    const float4* t4 = (const float4*)g_t;
    float4* z4 = (float4*)g_z;
    float4 sum = make_float4(0.f, 0.f, 0.f, 0.f);
    #pragma unroll 8
    for (int d = 0; d < DD; d++) {
        float4 v = t4[d * (HWSZ / 4) + hw4];
        sum.x += v.x; sum.y += v.y; sum.z += v.z; sum.w += v.w;
    }
    float4 sn = ((const float4*)sino)[hw4];
    float4 r = make_float4((sn.x - sum.x) * (1.f/DD), (sn.y - sum.y) * (1.f/DD),
                           (sn.z - sum.z) * (1.f/DD), (sn.w - sum.w) * (1.f/DD));
    #pragma unroll 8
    for (int d = 0; d < DD; d++) {
        float4 v = t4[d * (HWSZ / 4) + hw4];
        z4[d * (HWSZ / 4) + hw4] = make_float4(v.x + r.x, v.y + r.y, v.z + r.z, v.w + r.w);
    }
}

// ---------------- K2: fused sliding-window conv block ----------------
// Hidden planes stored parity-split: even-w at [row*17 + hw/2], odd-w at [306 + row*17 + hw/2].
__global__ __launch_bounds__(256, 2) void k_conv(
    const float* __restrict__ W1g, const float* __restrict__ B1g,
    const float* __restrict__ W2g, const float* __restrict__ B2g,
    const float* __restrict__ ntx, const float* __restrict__ nty,
    const float* __restrict__ ntz, const float* __restrict__ nt,
    int casc)
{
    extern __shared__ char sm[];
    ulonglong2* sHA = (ulonglong2*)(sm + OFF_HA);
    ulonglong2* sHB = (ulonglong2*)(sm + OFF_HB);
    float* sIn = (float*)(sm + OFF_IN);
    u64* sW1u = (u64*)(sm + OFF_W1);
    u64* sW2u = (u64*)(sm + OFF_W2);
    u64* sB1 = (u64*)(sm + OFF_B1);
    float* sB2 = (float*)(sm + OFF_B2);
    const ulonglong2* sW1v = (const ulonglong2*)sW1u;
    const ulonglong2* sW2v = (const ulonglong2*)sW2u;

    const int tid = threadIdx.x;
    const int b = blockIdx.z;                       // 0=dx 1=dy 2=dz 3=z
    const int h0 = blockIdx.y * TH, w0 = blockIdx.x * TW;

    if (tid < 108) {
        int k = tid >> 2, q = tid & 3;
        sW1u[k * 4 + q] = pack2(W1g[b*216 + (2*q)*27 + k], W1g[b*216 + (2*q+1)*27 + k]);
    } else if (tid < 216) {
        int t = tid - 108; int k = t >> 2, q = t & 3;
        sW2u[k * 4 + q] = pack2(W2g[b*216 + (2*q)*27 + k], W2g[b*216 + (2*q+1)*27 + k]);
    } else if (tid < 220) {
        int q = tid - 216;
        sB1[q] = pack2(B1g[b*8 + 2*q], B1g[b*8 + 2*q + 1]);
    } else if (tid == 220) {
        sB2[0] = B2g[b];
    }
    const float eta = ((b == 0) ? ntx : (b == 1) ? nty : (b == 2) ? ntz : nt)[casc];
    const float* oldv = (b == 0) ? g_p : (b == 1) ? g_q : (b == 2) ? g_s : g_t;
    float*       dst  = (b == 0) ? g_p : (b == 1) ? g_q : (b == 2) ? g_s : g_zb;

    auto load_elem = [&](int id, int j) -> float {
        int i = tid + j * 256;
        if (i >= 720) return 0.f;
        int lh = i / 36, lw = i - lh * 36;
        int gh = h0 + lh - 2, gw = w0 + lw - 2;
        float v = 0.f;
        if (id >= 0 && id < DD && gh >= 0 && gh < HH_ && gw >= 0 && gw < WW) {
            const float* zp = g_z + ((size_t)id * HH_ + gh) * WW + gw;
            if (b == 3) v = zp[0];
            else if (b == 0) { if (gw < WW - 1) v = zp[1] - zp[0]; }
            else if (b == 1) { if (gh < HH_ - 1) v = zp[WW] - zp[0]; }
            else             { if (id < DD - 1) v = zp[HWSZ] - zp[0]; }
        }
        return v;
    };
    auto pre_load = [&](int id, float* R) {
        #pragma unroll
        for (int j = 0; j < 3; j++) R[j] = load_elem(id, j);
    };
    auto sts_plane = [&](int id, const float* R) {
        float* dp = sIn + (id & 3) * NINP;
        #pragma unroll
        for (int j = 0; j < 3; j++) {
            int i = tid + j * 256;
            if (i < 720) {
                int lh = i / 36, lw = i - lh * 36;
                dp[lh * IWP + lw] = R[j];
            }
        }
    };
    auto fill_in = [&](int id) {
        float R[3]; pre_load(id, R); sts_plane(id, R);
    };

    // ---- conv1+relu for hidden planes hd1, hd1+1 (parity-split store) ----
    auto comp_pair = [&](int hd1) {
        const int hd2 = hd1 + 1;
        const bool v1 = (hd1 >= 0 && hd1 < DD);
        const bool v2 = (hd2 >= 0 && hd2 < DD);
        ulonglong2* HA1 = sHA + (hd1 & 3) * NHP;
        ulonglong2* HB1 = sHB + (hd1 & 3) * NHP;
        ulonglong2* HA2 = sHA + (hd2 & 3) * NHP;
        ulonglong2* HB2 = sHB + (hd2 & 3) * NHP;
        if (tid >= 216) return;
        const int r = tid / 12, seg = tid - 12 * r;
        const int hw0 = seg * 3;
        u64 acc1[3][4], acc2[3][4];
        #pragma unroll
        for (int j = 0; j < 3; j++)
            #pragma unroll
            for (int q = 0; q < 4; q++) { acc1[j][q] = sB1[q]; acc2[j][q] = sB1[q]; }
        #pragma unroll
        for (int kd = 0; kd < 3; kd++) {
            const float* p1 = sIn + ((hd1 - 1 + kd) & 3) * NINP;
            const float* p2 = sIn + ((hd2 - 1 + kd) & 3) * NINP;
            #pragma unroll
            for (int kh = 0; kh < 3; kh++) {
                int ro = (r + kh) * IWP + hw0;
                u64 va[5], vb[5];
                #pragma unroll
                for (int m = 0; m < 5; m++) {
                    float a = p1[ro + m], c = p2[ro + m];
                    va[m] = pack2(a, a);
                    vb[m] = pack2(c, c);
                }
                #pragma unroll
                for (int kw = 0; kw < 3; kw++) {
                    int k = kd * 9 + kh * 3 + kw;
                    ulonglong2 wA = sW1v[k * 2], wB = sW1v[k * 2 + 1];
                    #pragma unroll
                    for (int j = 0; j < 3; j++) {
                        acc1[j][0] = ffma2(wA.x, va[j + kw], acc1[j][0]);
                        acc1[j][1] = ffma2(wA.y, va[j + kw], acc1[j][1]);
                        acc1[j][2] = ffma2(wB.x, va[j + kw], acc1[j][2]);
                        acc1[j][3] = ffma2(wB.y, va[j + kw], acc1[j][3]);
                        acc2[j][0] = ffma2(wA.x, vb[j + kw], acc2[j][0]);
                        acc2[j][1] = ffma2(wA.y, vb[j + kw], acc2[j][1]);
                        acc2[j][2] = ffma2(wB.x, vb[j + kw], acc2[j][2]);
                        acc2[j][3] = ffma2(wB.y, vb[j + kw], acc2[j][3]);
                    }
                }
            }
        }
        #pragma unroll
        for (int j = 0; j < 3; j++) {
            int hw = hw0 + j;
            if (hw >= HWP) continue;
            int gh = h0 + r - 1, gw = w0 + hw - 1;
            bool okxy = (gh >= 0 && gh < HH_ && gw >= 0 && gw < WW);
            int idx = r * HROW + (hw >> 1) + ((hw & 1) ? HODD : 0);
            u64 r1[4], r2[4];
            #pragma unroll
            for (int q = 0; q < 4; q++) {
                float a, c;
                unpack2(acc1[j][q], a, c);
                r1[q] = (okxy && v1) ? pack2(fmaxf(a, 0.f), fmaxf(c, 0.f)) : 0ULL;
                unpack2(acc2[j][q], a, c);
                r2[q] = (okxy && v2) ? pack2(fmaxf(a, 0.f), fmaxf(c, 0.f)) : 0ULL;
            }
            HA1[idx] = make_ulonglong2(r1[0], r1[1]);
            HB1[idx] = make_ulonglong2(r1[2], r1[3]);
            HA2[idx] = make_ulonglong2(r2[0], r2[1]);
            HB2[idx] = make_ulonglong2(r2[2], r2[3]);
        }
    };

    // ---- conv2 + momentum update; thread -> 2 planes x 2 adjacent w ----
    auto do_out2 = [&](int od) {
        const int c = tid & 15;          // w-pair: ow = 2c, 2c+1
        const int r = tid >> 4;          // 0..15
        const ulonglong2* HAp[4]; const ulonglong2* HBp[4];
        #pragma unroll
        for (int pp = 0; pp < 4; pp++) {
            HAp[pp] = sHA + ((od - 1 + pp) & 3) * NHP;
            HBp[pp] = sHB + ((od - 1 + pp) & 3) * NHP;
        }
        u64 acc[2][2][4];                // [s][wsel][q]
        #pragma unroll
        for (int s = 0; s < 2; s++)
            #pragma unroll
            for (int ws = 0; ws < 2; ws++)
                #pragma unroll
                for (int q = 0; q < 4; q++) acc[s][ws][q] = 0ULL;
        #pragma unroll
        for (int kh = 0; kh < 3; kh++) {
            int rowb = (r + kh) * HROW + c;
            #pragma unroll
            for (int pp = 0; pp < 4; pp++) {
                // m: hidden w position 2c+m ; m0=E[c], m1=O[c], m2=E[c+1], m3=O[c+1]
                ulonglong2 hA[4], hB[4];
                hA[0] = HAp[pp][rowb];            hB[0] = HBp[pp][rowb];
                hA[1] = HAp[pp][HODD + rowb];     hB[1] = HBp[pp][HODD + rowb];
                hA[2] = HAp[pp][rowb + 1];        hB[2] = HBp[pp][rowb + 1];
                hA[3] = HAp[pp][HODD + rowb + 1]; hB[3] = HBp[pp][HODD + rowb + 1];
                #pragma unroll
                for (int s = 0; s < 2; s++) {
                    int kd = pp - s;
                    if (kd < 0 || kd > 2) continue;
                    #pragma unroll
                    for (int kw = 0; kw < 3; kw++) {
                        int k = kd * 9 + kh * 3 + kw;
                        ulonglong2 wa = sW2v[k * 2], wb = sW2v[k * 2 + 1];
                        #pragma unroll
                        for (int ws = 0; ws < 2; ws++) {
                            int m = kw + ws;
                            acc[s][ws][0] = ffma2(wa.x, hA[m].x, acc[s][ws][0]);
                            acc[s][ws][1] = ffma2(wa.y, hA[m].y, acc[s][ws][1]);
                            acc[s][ws][2] = ffma2(wb.x, hB[m].x, acc[s][ws][2]);
                            acc[s][ws][3] = ffma2(wb.y, hB[m].y, acc[s][ws][3]);
                        }
                    }
                }
            }
        }
        float bb = sB2[0];
        #pragma unroll
        for (int s = 0; s < 2; s++)
        #pragma unroll
        for (int ws = 0; ws < 2; ws++) {
            float sum = bb;
            #pragma unroll
            for (int q = 0; q < 4; q++) {
                float a, cc; unpack2(acc[s][ws][q], a, cc);
                sum += a + cc;
            }
            size_t gi = ((size_t)(od + s) * HH_ + (h0 + r)) * WW + (w0 + 2 * c + ws);
            float old = oldv[gi];
            dst[gi] = old + eta * (old - sum);
        }
    };

    // ---- prologue ----
    fill_in(-1); fill_in(0); fill_in(1); fill_in(2);
    __syncthreads();
    comp_pair(-1);                 // hidden -1 (zeros), 0
    __syncthreads();
    float R[6];
    fill_in(3);
    pre_load(4, R); pre_load(5, R + 3);
    __syncthreads();

    // ---- main loop: 2 barriers / 2 planes; LDG overlapped with compute ----
    for (int od = 0; od < DD; od += 2) {
        comp_pair(od + 1);          // hidden od+1, od+2 (reads input od..od+3)
        __syncthreads();
        sts_plane(od + 4, R);
        sts_plane(od + 5, R + 3);
        pre_load(od + 6, R);
        pre_load(od + 7, R + 3);
        do_out2(od);                // reads hidden od-1..od+2
        __syncthreads();
    }
}

// ---------------- K3: t = divT(p,q,s) + z_ (float4) ----------------
__global__ void k_tupd(float* __restrict__ out, int casc) {
    int i4 = blockIdx.x * blockDim.x + threadIdx.x;
    if (i4 >= DHW / 4) return;
    int i = i4 * 4;
    int w = i & (WW - 1);
    int h = (i >> 8) & (HH_ - 1);
    int d = i >> 16;
    const float4* p4 = (const float4*)g_p;
    const float4* q4 = (const float4*)g_q;
    const float4* s4 = (const float4*)g_s;
    float4 v = ((const float4*)g_zb)[i4];
    float4 pc = p4[i4];
    float pm = (w > 0) ? g_p[i - 1] : 0.f;
    v.x += pm   - pc.x;
    v.y += pc.x - pc.y;
    v.z += pc.y - pc.z;
    v.w += pc.z - ((w + 3 < WW - 1) ? pc.w : 0.f);
    float4 qc = q4[i4];
    if (h < HH_ - 1) { v.x -= qc.x; v.y -= qc.y; v.z -= qc.z; v.w -= qc.w; }
    if (h > 0) {
        float4 qu = q4[i4 - WW / 4];
        v.x += qu.x; v.y += qu.y; v.z += qu.z; v.w += qu.w;
    }
    float4 sc = s4[i4];
    if (d < DD - 1) { v.x -= sc.x; v.y -= sc.y; v.z -= sc.z; v.w -= sc.w; }
    if (d > 0) {
        float4 su = s4[i4 - HWSZ / 4];
        v.x += su.x; v.y += su.y; v.z += su.z; v.w += su.w;
    }
    ((float4*)g_t)[i4] = v;
    ((float4*)(out + (size_t)(casc + 1) * DHW))[i4] = v;
}

extern "C" void kernel_launch(void* const* d_in, const int* in_sizes, int n_in,
                              void* d_out, int out_size) {
    const float* image = (const float*)d_in[0];
    const float* sino  = (const float*)d_in[1];
    const float* W1    = (const float*)d_in[2];
    const float* B1    = (const float*)d_in[3];
    const float* W2    = (const float*)d_in[4];
    const float* B2    = (const float*)d_in[5];
    const float* ntx   = (const float*)d_in[6];
    const float* nty   = (const float*)d_in[7];
    const float* ntz   = (const float*)d_in[8];
    const float* nt    = (const float*)d_in[9];
    float* out = (float*)d_out;

    cudaFuncSetAttribute((const void*)k_conv,
                         cudaFuncAttributeMaxDynamicSharedMemorySize, SMEM_BYTES);

    k_init<<<(DHW / 4) / 256, 256>>>(image, out);
    for (int c = 0; c < CASC; c++) {
        k_z<<<(HWSZ / 4) / 256, 256>>>(sino);
        dim3 grid(WW / TW, HH_ / TH, 4);   // 512 CTAs
        k_conv<<<grid, 256, SMEM_BYTES>>>(W1, B1, W2, B2, ntx, nty, ntz, nt, c);
        k_tupd<<<(DHW / 4) / 256, 256>>>(out, c);
    }
}